// round 12
// baseline (speedup 1.0000x reference)
#include <cuda_runtime.h>
#include <cuda_fp16.h>
#include <cstdint>

// DistMap: d[b,i,j] = aa[b,i] + bb[b,j] - 2 * sum_c a[b,c,i]*b[b,c,j]
// a: [B=4, C=64, N=4096] fp32, b: [4, 64, 4096], out: [4, 4096, 4096] fp32
// mma.sync.m16n8k16 fp16 (fp32 accum; fp16 mantissa == tf32 mantissa, N(0,1)).
// CTA covers TWO adjacent 128x128 j-tiles at fixed i0:
//   A tile loaded once; B tiles double-buffered (B1 load overlaps tile0 stores).
// 4 warps (64x64 warp tiles), j-range in 2 halves (acc 64 regs) -> 3 CTAs/SM.
// LDT=136: conflict-free fragment LDS. Logical-n permutation -> float4 stores.

#define C_DIM 64
#define NN    4096
#define TILE  128
#define JITER 2
#define NTHREADS 128
#define LDT   136
#define KW    32          // 64 k-values packed as 32 half2 words

#define SMEM_WORDS (KW * LDT)
#define SMEM_TOTAL (3 * SMEM_WORDS * 4)   // As + Bs0 + Bs1

// ---------------- norms precompute (exact fp32) ----------------

__device__ float g_aa[4 * NN];
__device__ float g_bb[4 * NN];

__global__ void norms_kernel(const float* __restrict__ A, const float* __restrict__ B) {
    int idx = blockIdx.x * blockDim.x + threadIdx.x;    // 0..32767
    int which = idx >> 14;
    int r = idx & 16383;                                 // b*4096 + i
    const float* src = (which ? B : A) + (size_t)(r >> 12) * (C_DIM * NN) + (r & 4095);
    float s = 0.0f;
#pragma unroll
    for (int c = 0; c < C_DIM; c++) { float v = src[(size_t)c * NN]; s += v * v; }
    (which ? g_bb : g_aa)[r] = s;
}

// ---------------- helpers ----------------

__device__ __forceinline__ uint32_t pack_h2(float x, float y) {
    __half2 h = __floats2half2_rn(x, y);
    return *(uint32_t*)&h;
}

__device__ __forceinline__ void mma_f16(float c[4], const uint32_t a[4], const uint32_t b[2]) {
    asm volatile(
        "mma.sync.aligned.m16n8k16.row.col.f32.f16.f16.f32 "
        "{%0,%1,%2,%3}, {%4,%5,%6,%7}, {%8,%9}, {%0,%1,%2,%3};"
        : "+f"(c[0]), "+f"(c[1]), "+f"(c[2]), "+f"(c[3])
        : "r"(a[0]), "r"(a[1]), "r"(a[2]), "r"(a[3]), "r"(b[0]), "r"(b[1]));
}

// load one 128-wide B tile (tf32-equivalent fp16 pack) into Bs with the
// logical-n permutation. 1024 (kw,col4) groups, 128 threads -> 8 iters.
__device__ __forceinline__ void load_b_tile(const float* __restrict__ Bb, int j0t,
                                            uint32_t* __restrict__ Bs, int tid) {
#pragma unroll
    for (int it = 0; it < 8; it++) {
        int t4   = tid + it * NTHREADS;
        int kw   = t4 >> 5;
        int col4 = (t4 & 31) << 2;
        const float* b0p = &Bb[(size_t)(2 * kw) * NN + j0t + col4];
        float4 vb0 = *(const float4*)b0p;
        float4 vb1 = *(const float4*)(b0p + NN);
        int h     = col4 >> 6;
        int hh    = (col4 >> 4) & 3;
        int t     = (col4 >> 2) & 3;
        int nbase = 64 * h + 16 * hh + 2 * t;
        uint2 lo = { pack_h2(vb0.x, vb1.x), pack_h2(vb0.y, vb1.y) };
        uint2 hi = { pack_h2(vb0.z, vb1.z), pack_h2(vb0.w, vb1.w) };
        *(uint2*)&Bs[kw * LDT + nbase]     = lo;
        *(uint2*)&Bs[kw * LDT + nbase + 8] = hi;
    }
}

// ---------------- main kernel ----------------

__global__ __launch_bounds__(NTHREADS, 3)
void distmap_mma_kernel(const float* __restrict__ A,   // [4, 64, 4096]
                        const float* __restrict__ Bm,  // [4, 64, 4096]
                        float* __restrict__ D)         // [4, 4096, 4096]
{
    extern __shared__ __align__(16) char smem[];
    uint32_t* As  = (uint32_t*)smem;
    uint32_t* Bs0 = As + SMEM_WORDS;
    uint32_t* Bs1 = Bs0 + SMEM_WORDS;

    const int tid  = threadIdx.x;
    const int lane = tid & 31;
    const int wid  = tid >> 5;    // 0..3
    const int gid  = lane >> 2;   // 0..7
    const int tig  = lane & 3;    // 0..3
    const int i_w  = (wid >> 1) * 64;
    const int j_w  = (wid & 1) * 64;

    const int b      = blockIdx.z;
    const int i0     = blockIdx.y * TILE;
    const int j0base = blockIdx.x * (TILE * JITER);

    const float* Ab = A  + (size_t)b * C_DIM * NN;
    const float* Bb = Bm + (size_t)b * C_DIM * NN;

    // ---- A tile (once) + B tile 0 ----
#pragma unroll
    for (int it = 0; it < 8; it++) {
        int t4   = tid + it * NTHREADS;
        int kw   = t4 >> 5;
        int col4 = (t4 & 31) << 2;
        const float* a0p = &Ab[(size_t)(2 * kw) * NN + i0 + col4];
        float4 va0 = *(const float4*)a0p;
        float4 va1 = *(const float4*)(a0p + NN);
        uint4 wa = { pack_h2(va0.x, va1.x), pack_h2(va0.y, va1.y),
                     pack_h2(va0.z, va1.z), pack_h2(va0.w, va1.w) };
        *(uint4*)&As[kw * LDT + col4] = wa;
    }
    load_b_tile(Bb, j0base, Bs0, tid);
    __syncthreads();

    // aa values for the warp's 8 i-rows (hoisted)
    float aav[4][2];
#pragma unroll
    for (int mt = 0; mt < 4; mt++) {
        aav[mt][0] = g_aa[b * NN + i0 + i_w + mt * 16 + gid];
        aav[mt][1] = g_aa[b * NN + i0 + i_w + mt * 16 + 8 + gid];
    }

    float* Dbase = D + (size_t)b * NN * NN;

#pragma unroll
    for (int jt = 0; jt < JITER; jt++) {
        const uint32_t* Bs = jt ? Bs1 : Bs0;
        const int j0 = j0base + jt * TILE;

        // two halves of the warp's 64-wide j-range (4 n-tiles each)
#pragma unroll
        for (int nh = 0; nh < 2; nh++) {
            float acc[4][4][4];
#pragma unroll
            for (int mt = 0; mt < 4; mt++)
#pragma unroll
                for (int nt = 0; nt < 4; nt++)
#pragma unroll
                    for (int e = 0; e < 4; e++) acc[mt][nt][e] = 0.0f;

#pragma unroll
            for (int s = 0; s < 4; s++) {
                const int kwb = s * 8;
                uint32_t afr[4][4];
#pragma unroll
                for (int mt = 0; mt < 4; mt++) {
                    int ib = i_w + mt * 16 + gid;
                    afr[mt][0] = As[(kwb + tig)     * LDT + ib];
                    afr[mt][1] = As[(kwb + tig)     * LDT + ib + 8];
                    afr[mt][2] = As[(kwb + 4 + tig) * LDT + ib];
                    afr[mt][3] = As[(kwb + 4 + tig) * LDT + ib + 8];
                }
                uint32_t bfr[4][2];
#pragma unroll
                for (int nt = 0; nt < 4; nt++) {
                    int jb = j_w + (nh * 4 + nt) * 8 + gid;   // logical n
                    bfr[nt][0] = Bs[(kwb + tig)     * LDT + jb];
                    bfr[nt][1] = Bs[(kwb + 4 + tig) * LDT + jb];
                }
#pragma unroll
                for (int mt = 0; mt < 4; mt++)
#pragma unroll
                    for (int nt = 0; nt < 4; nt++)
                        mma_f16(acc[mt][nt], afr[mt], bfr[nt]);
            }

            // After tile0 mainloop half 1: kick off B1 load before the stores,
            // so B1's L2-latency drains under the STG burst.
            if (jt == 0 && nh == 1)
                load_b_tile(Bb, j0base + TILE, Bs1, tid);

            // epilogue for this half
            float4 bbv[2];
#pragma unroll
            for (int np = 0; np < 2; np++)
                bbv[np] = *(const float4*)&g_bb[b * NN + j0 + j_w + (2 * nh + np) * 16 + 4 * tig];

#pragma unroll
            for (int mt = 0; mt < 4; mt++) {
#pragma unroll
                for (int rh = 0; rh < 2; rh++) {
                    int row = i0 + i_w + mt * 16 + rh * 8 + gid;
                    float aa = aav[mt][rh];
                    float* Drow = &Dbase[(size_t)row * NN + j0 + j_w + 4 * tig];
#pragma unroll
                    for (int np = 0; np < 2; np++) {
                        float4 o;
                        o.x = aa + bbv[np].x - 2.0f * acc[mt][2 * np][rh * 2 + 0];
                        o.y = aa + bbv[np].y - 2.0f * acc[mt][2 * np][rh * 2 + 1];
                        o.z = aa + bbv[np].z - 2.0f * acc[mt][2 * np + 1][rh * 2 + 0];
                        o.w = aa + bbv[np].w - 2.0f * acc[mt][2 * np + 1][rh * 2 + 1];
                        *(float4*)&Drow[(2 * nh + np) * 16] = o;
                    }
                }
            }
        }

        if (jt == 0) __syncthreads();   // B1 STS complete before tile1 reads it
    }
}

// ---------------- launch ----------------

extern "C" void kernel_launch(void* const* d_in, const int* in_sizes, int n_in,
                              void* d_out, int out_size)
{
    const float* a = (const float*)d_in[0];
    const float* b = (const float*)d_in[1];
    float* out = (float*)d_out;

    cudaFuncSetAttribute(distmap_mma_kernel,
                         cudaFuncAttributeMaxDynamicSharedMemorySize, SMEM_TOTAL);

    norms_kernel<<<128, 256>>>(a, b);
    dim3 grid(NN / (TILE * JITER), NN / TILE, 4);   // (16, 32, 4)
    distmap_mma_kernel<<<grid, NTHREADS, SMEM_TOTAL>>>(a, b, out);
}

// round 13
// speedup vs baseline: 1.2016x; 1.2016x over previous
#include <cuda_runtime.h>
#include <cuda_fp16.h>
#include <cstdint>

// DistMap: d[b,i,j] = aa[b,i] + bb[b,j] - 2 * sum_c a[b,c,i]*b[b,c,j]
// a: [B=4, C=64, N=4096] fp32, b: [4, 64, 4096], out: [4, 4096, 4096] fp32
// mma.sync.m16n8k16 fp16 (fp32 accum; fp16 mantissa == tf32 mantissa, N(0,1)).
// Pre-convert kernel packs fp32 -> half2 k-pairs:
//   pa[b][kw][i] = half2(a[b][2kw][i], a[b][2kw+1][i])
//   pb[b][kw][n] = same for b, with the logical-n permutation baked in (period 64)
// Main kernel: CTA 128x128, 4 warps (64x64 warp tiles), K=64 smem-resident.
// Tiles loaded with cp.async.cg (16B, L1-bypassed). j-range in 2 halves
// (live acc = 64 regs) -> 3 CTAs/SM. LDT=136: conflict-free fragment LDS.
// Epilogue: float4 coalesced stores.

#define C_DIM 64
#define NN    4096
#define TILE  128
#define NTHREADS 128
#define LDT   136
#define KW    32          // 64 k-values as 32 half2 words

#define SMEM_WORDS (KW * LDT)
#define SMEM_TOTAL (2 * SMEM_WORDS * 4)

// ---------------- device scratch ----------------

__device__ float    g_aa[4 * NN];
__device__ float    g_bb[4 * NN];
__device__ uint32_t g_pa[4 * KW * NN];   // 2 MB
__device__ uint32_t g_pb[4 * KW * NN];   // 2 MB

// ---------------- norms precompute (exact fp32) ----------------

__global__ void norms_kernel(const float* __restrict__ A, const float* __restrict__ B) {
    int idx = blockIdx.x * blockDim.x + threadIdx.x;    // 0..32767
    int which = idx >> 14;
    int r = idx & 16383;                                 // b*4096 + i
    const float* src = (which ? B : A) + (size_t)(r >> 12) * (C_DIM * NN) + (r & 4095);
    float s = 0.0f;
#pragma unroll
    for (int c = 0; c < C_DIM; c++) { float v = src[(size_t)c * NN]; s += v * v; }
    (which ? g_bb : g_aa)[r] = s;
}

// ---------------- fp16 pack + permute precompute ----------------

__device__ __forceinline__ uint32_t pack_h2(float x, float y) {
    __half2 h = __floats2half2_rn(x, y);
    return *(uint32_t*)&h;
}

// logical-n permutation (period 64 in j):
//   n = (j & ~63) | 16*((j>>4)&3) + 8*((j>>1)&1) + 2*((j>>2)&3) + (j&1)
__device__ __forceinline__ int perm_n(int j) {
    return (j & ~63) | (16 * ((j >> 4) & 3) + 8 * ((j >> 1) & 1)
                       + 2 * ((j >> 2) & 3) + (j & 1));
}

__global__ void convert_kernel(const float* __restrict__ A, const float* __restrict__ B) {
    int idx = blockIdx.x * blockDim.x + threadIdx.x;    // 0..524287
    int b   = idx >> 17;
    int r   = idx & 131071;
    int kw  = r >> 12;
    int col = r & 4095;
    const float* Ab = A + (size_t)b * C_DIM * NN + (size_t)(2 * kw) * NN;
    const float* Bb = B + (size_t)b * C_DIM * NN + (size_t)(2 * kw) * NN;
    int base = (b * KW + kw) * NN;
    g_pa[base + col]         = pack_h2(Ab[col], Ab[col + NN]);
    g_pb[base + perm_n(col)] = pack_h2(Bb[col], Bb[col + NN]);
}

// ---------------- helpers ----------------

__device__ __forceinline__ uint32_t smem_u32(const void* p) {
    uint32_t a;
    asm("{ .reg .u64 t; cvta.to.shared.u64 t, %1; cvt.u32.u64 %0, t; }" : "=r"(a) : "l"(p));
    return a;
}

#define CP_ASYNC16(dst, src) \
    asm volatile("cp.async.cg.shared.global [%0], [%1], 16;" :: "r"(dst), "l"(src))
#define CP_COMMIT() asm volatile("cp.async.commit_group;" ::: "memory")
#define CP_WAIT0()  asm volatile("cp.async.wait_group 0;" ::: "memory")

__device__ __forceinline__ void mma_f16(float c[4], const uint32_t a[4], const uint32_t b[2]) {
    asm volatile(
        "mma.sync.aligned.m16n8k16.row.col.f32.f16.f16.f32 "
        "{%0,%1,%2,%3}, {%4,%5,%6,%7}, {%8,%9}, {%0,%1,%2,%3};"
        : "+f"(c[0]), "+f"(c[1]), "+f"(c[2]), "+f"(c[3])
        : "r"(a[0]), "r"(a[1]), "r"(a[2]), "r"(a[3]), "r"(b[0]), "r"(b[1]));
}

// ---------------- main kernel ----------------

__global__ __launch_bounds__(NTHREADS, 3)
void distmap_mma_kernel(float* __restrict__ D)   // [4, 4096, 4096]
{
    extern __shared__ __align__(16) char smem[];
    uint32_t* As = (uint32_t*)smem;
    uint32_t* Bs = As + SMEM_WORDS;

    const int tid  = threadIdx.x;
    const int lane = tid & 31;
    const int wid  = tid >> 5;    // 0..3
    const int gid  = lane >> 2;   // 0..7
    const int tig  = lane & 3;    // 0..3
    const int i_w  = (wid >> 1) * 64;
    const int j_w  = (wid & 1) * 64;

    const int b  = blockIdx.z;
    const int i0 = blockIdx.y * TILE;
    const int j0 = blockIdx.x * TILE;

    const uint32_t* pa_b = g_pa + (size_t)b * KW * NN;
    const uint32_t* pb_b = g_pb + (size_t)b * KW * NN;
    const uint32_t as_u = smem_u32(As);
    const uint32_t bs_u = smem_u32(Bs);

    // ---- tile loads: 1024 16B-chunks per tile, 128 threads -> 8 iters ----
#pragma unroll
    for (int it = 0; it < 8; it++) {
        int t  = tid + it * NTHREADS;     // 0..1023
        int kw = t >> 5;
        int ch = (t & 31) << 2;           // word offset in row (4 words = 16B)
        CP_ASYNC16(as_u + (uint32_t)(kw * LDT + ch) * 4u, pa_b + kw * NN + i0 + ch);
        CP_ASYNC16(bs_u + (uint32_t)(kw * LDT + ch) * 4u, pb_b + kw * NN + j0 + ch);
    }
    CP_COMMIT();

    // aa values for the warp's 8 i-rows (hoisted; overlaps with cp.async drain)
    float aav[4][2];
#pragma unroll
    for (int mt = 0; mt < 4; mt++) {
        aav[mt][0] = g_aa[b * NN + i0 + i_w + mt * 16 + gid];
        aav[mt][1] = g_aa[b * NN + i0 + i_w + mt * 16 + 8 + gid];
    }

    CP_WAIT0();
    __syncthreads();

    float* Dbase = D + (size_t)b * NN * NN;

    // ---- two halves of the warp's 64-wide j-range (4 n-tiles each) ----
#pragma unroll
    for (int nh = 0; nh < 2; nh++) {
        float acc[4][4][4];
#pragma unroll
        for (int mt = 0; mt < 4; mt++)
#pragma unroll
            for (int nt = 0; nt < 4; nt++)
#pragma unroll
                for (int e = 0; e < 4; e++) acc[mt][nt][e] = 0.0f;

#pragma unroll
        for (int s = 0; s < 4; s++) {
            const int kwb = s * 8;
            uint32_t afr[4][4];
#pragma unroll
            for (int mt = 0; mt < 4; mt++) {
                int ib = i_w + mt * 16 + gid;
                afr[mt][0] = As[(kwb + tig)     * LDT + ib];
                afr[mt][1] = As[(kwb + tig)     * LDT + ib + 8];
                afr[mt][2] = As[(kwb + 4 + tig) * LDT + ib];
                afr[mt][3] = As[(kwb + 4 + tig) * LDT + ib + 8];
            }
            uint32_t bfr[4][2];
#pragma unroll
            for (int nt = 0; nt < 4; nt++) {
                int jb = j_w + (nh * 4 + nt) * 8 + gid;   // logical n index
                bfr[nt][0] = Bs[(kwb + tig)     * LDT + jb];
                bfr[nt][1] = Bs[(kwb + 4 + tig) * LDT + jb];
            }
#pragma unroll
            for (int mt = 0; mt < 4; mt++)
#pragma unroll
                for (int nt = 0; nt < 4; nt++)
                    mma_f16(acc[mt][nt], afr[mt], bfr[nt]);
        }

        // epilogue for this half: float4 stores at j = j0+j_w+(2nh+np)*16+4tig
        float4 bbv[2];
#pragma unroll
        for (int np = 0; np < 2; np++)
            bbv[np] = *(const float4*)&g_bb[b * NN + j0 + j_w + (2 * nh + np) * 16 + 4 * tig];

#pragma unroll
        for (int mt = 0; mt < 4; mt++) {
#pragma unroll
            for (int rh = 0; rh < 2; rh++) {
                int row = i0 + i_w + mt * 16 + rh * 8 + gid;
                float aa = aav[mt][rh];
                float* Drow = &Dbase[(size_t)row * NN + j0 + j_w + 4 * tig];
#pragma unroll
                for (int np = 0; np < 2; np++) {
                    float4 o;
                    o.x = aa + bbv[np].x - 2.0f * acc[mt][2 * np][rh * 2 + 0];
                    o.y = aa + bbv[np].y - 2.0f * acc[mt][2 * np][rh * 2 + 1];
                    o.z = aa + bbv[np].z - 2.0f * acc[mt][2 * np + 1][rh * 2 + 0];
                    o.w = aa + bbv[np].w - 2.0f * acc[mt][2 * np + 1][rh * 2 + 1];
                    *(float4*)&Drow[(2 * nh + np) * 16] = o;
                }
            }
        }
    }
}

// ---------------- launch ----------------

extern "C" void kernel_launch(void* const* d_in, const int* in_sizes, int n_in,
                              void* d_out, int out_size)
{
    const float* a = (const float*)d_in[0];
    const float* b = (const float*)d_in[1];
    float* out = (float*)d_out;

    cudaFuncSetAttribute(distmap_mma_kernel,
                         cudaFuncAttributeMaxDynamicSharedMemorySize, SMEM_TOTAL);

    norms_kernel<<<128, 256>>>(a, b);
    convert_kernel<<<2048, 256>>>(a, b);
    dim3 grid(NN / TILE, NN / TILE, 4);   // (32, 32, 4)
    distmap_mma_kernel<<<grid, NTHREADS, SMEM_TOTAL>>>(out);
}

// round 15
// speedup vs baseline: 1.3903x; 1.1571x over previous
#include <cuda_runtime.h>
#include <cuda_fp16.h>
#include <cstdint>

// DistMap: d[b,i,j] = aa[b,i] + bb[b,j] - 2 * sum_c a[b,c,i]*b[b,c,j]
// a: [B=4, C=64, N=4096] fp32, b: [4, 64, 4096], out: [4, 4096, 4096] fp32
// mma.sync.m16n8k16 fp16 (fp32 accum; fp16 mantissa == tf32 mantissa, N(0,1)).
// ONE fused prep kernel: per (a|b, batch, col) column computes the exact fp32
// norm AND packs 32 half2 k-pair words (pb gets the logical-n permutation).
// Main kernel: CTA 128x128, 4 warps (64x64 warp tiles), K=64 smem-resident,
// cp.async.cg tile loads (L1-bypassed), j-range in 2 halves (acc 64 regs)
// -> 3 CTAs/SM. LDT=136 conflict-free fragment LDS. float4 st.global.cs stores.

#define C_DIM 64
#define NN    4096
#define TILE  128
#define NTHREADS 128
#define LDT   136
#define KW    32          // 64 k-values as 32 half2 words

#define SMEM_WORDS (KW * LDT)
#define SMEM_TOTAL (2 * SMEM_WORDS * 4)

// ---------------- device scratch ----------------

__device__ float    g_aa[4 * NN];
__device__ float    g_bb[4 * NN];
__device__ uint32_t g_pa[4 * KW * NN];   // 2 MB
__device__ uint32_t g_pb[4 * KW * NN];   // 2 MB

// ---------------- helpers ----------------

__device__ __forceinline__ uint32_t pack_h2(float x, float y) {
    __half2 h = __floats2half2_rn(x, y);
    return *(uint32_t*)&h;
}

// logical-n permutation (period 64 in j):
__device__ __forceinline__ int perm_n(int j) {
    return (j & ~63) | (16 * ((j >> 4) & 3) + 8 * ((j >> 1) & 1)
                       + 2 * ((j >> 2) & 3) + (j & 1));
}

__device__ __forceinline__ uint32_t smem_u32(const void* p) {
    uint32_t a;
    asm("{ .reg .u64 t; cvta.to.shared.u64 t, %1; cvt.u32.u64 %0, t; }" : "=r"(a) : "l"(p));
    return a;
}

#define CP_ASYNC16(dst, src) \
    asm volatile("cp.async.cg.shared.global [%0], [%1], 16;" :: "r"(dst), "l"(src))
#define CP_COMMIT() asm volatile("cp.async.commit_group;" ::: "memory")
#define CP_WAIT0()  asm volatile("cp.async.wait_group 0;" ::: "memory")

__device__ __forceinline__ void mma_f16(float c[4], const uint32_t a[4], const uint32_t b[2]) {
    asm volatile(
        "mma.sync.aligned.m16n8k16.row.col.f32.f16.f16.f32 "
        "{%0,%1,%2,%3}, {%4,%5,%6,%7}, {%8,%9}, {%0,%1,%2,%3};"
        : "+f"(c[0]), "+f"(c[1]), "+f"(c[2]), "+f"(c[3])
        : "r"(a[0]), "r"(a[1]), "r"(a[2]), "r"(a[3]), "r"(b[0]), "r"(b[1]));
}

// ---------------- fused prep: norms + fp16 pack (+ permutation for b) ----------------

__global__ void prep_kernel(const float* __restrict__ A, const float* __restrict__ B) {
    int idx = blockIdx.x * blockDim.x + threadIdx.x;    // 0..32767
    int which = idx >> 14;                              // 0 = a, 1 = b
    int r   = idx & 16383;                              // b*4096 + col
    int bb  = r >> 12;
    int col = r & 4095;
    const float* src = (which ? B : A) + (size_t)bb * C_DIM * NN + col;

    float v[C_DIM];
    float s = 0.0f;
#pragma unroll
    for (int c = 0; c < C_DIM; c++) {
        v[c] = src[(size_t)c * NN];
        s += v[c] * v[c];
    }

    uint32_t* dst = (which ? g_pb : g_pa) + (size_t)bb * KW * NN;
    int outcol = which ? perm_n(col) : col;
#pragma unroll
    for (int kw = 0; kw < KW; kw++)
        dst[(size_t)kw * NN + outcol] = pack_h2(v[2 * kw], v[2 * kw + 1]);

    (which ? g_bb : g_aa)[r] = s;
}

// ---------------- main kernel ----------------

__global__ __launch_bounds__(NTHREADS, 3)
void distmap_mma_kernel(float* __restrict__ D)   // [4, 4096, 4096]
{
    extern __shared__ __align__(16) char smem[];
    uint32_t* As = (uint32_t*)smem;
    uint32_t* Bs = As + SMEM_WORDS;

    const int tid  = threadIdx.x;
    const int lane = tid & 31;
    const int wid  = tid >> 5;    // 0..3
    const int gid  = lane >> 2;   // 0..7
    const int tig  = lane & 3;    // 0..3
    const int i_w  = (wid >> 1) * 64;
    const int j_w  = (wid & 1) * 64;

    const int b  = blockIdx.z;
    const int i0 = blockIdx.y * TILE;
    const int j0 = blockIdx.x * TILE;

    const uint32_t* pa_b = g_pa + (size_t)b * KW * NN;
    const uint32_t* pb_b = g_pb + (size_t)b * KW * NN;
    const uint32_t as_u = smem_u32(As);
    const uint32_t bs_u = smem_u32(Bs);

    // ---- tile loads: 1024 16B-chunks per tile, 128 threads -> 8 iters ----
#pragma unroll
    for (int it = 0; it < 8; it++) {
        int t  = tid + it * NTHREADS;     // 0..1023
        int kw = t >> 5;
        int ch = (t & 31) << 2;           // word offset (4 words = 16B)
        CP_ASYNC16(as_u + (uint32_t)(kw * LDT + ch) * 4u, pa_b + kw * NN + i0 + ch);
        CP_ASYNC16(bs_u + (uint32_t)(kw * LDT + ch) * 4u, pb_b + kw * NN + j0 + ch);
    }
    CP_COMMIT();

    // aa values for the warp's 8 i-rows (overlaps the cp.async drain)
    float aav[4][2];
#pragma unroll
    for (int mt = 0; mt < 4; mt++) {
        aav[mt][0] = g_aa[b * NN + i0 + i_w + mt * 16 + gid];
        aav[mt][1] = g_aa[b * NN + i0 + i_w + mt * 16 + 8 + gid];
    }

    CP_WAIT0();
    __syncthreads();

    float* Dbase = D + (size_t)b * NN * NN;

    // ---- two halves of the warp's 64-wide j-range (4 n-tiles each) ----
#pragma unroll
    for (int nh = 0; nh < 2; nh++) {
        float acc[4][4][4];
#pragma unroll
        for (int mt = 0; mt < 4; mt++)
#pragma unroll
            for (int nt = 0; nt < 4; nt++)
#pragma unroll
                for (int e = 0; e < 4; e++) acc[mt][nt][e] = 0.0f;

#pragma unroll
        for (int s = 0; s < 4; s++) {
            const int kwb = s * 8;
            uint32_t afr[4][4];
#pragma unroll
            for (int mt = 0; mt < 4; mt++) {
                int ib = i_w + mt * 16 + gid;
                afr[mt][0] = As[(kwb + tig)     * LDT + ib];
                afr[mt][1] = As[(kwb + tig)     * LDT + ib + 8];
                afr[mt][2] = As[(kwb + 4 + tig) * LDT + ib];
                afr[mt][3] = As[(kwb + 4 + tig) * LDT + ib + 8];
            }
            uint32_t bfr[4][2];
#pragma unroll
            for (int nt = 0; nt < 4; nt++) {
                int jb = j_w + (nh * 4 + nt) * 8 + gid;   // logical n index
                bfr[nt][0] = Bs[(kwb + tig)     * LDT + jb];
                bfr[nt][1] = Bs[(kwb + 4 + tig) * LDT + jb];
            }
#pragma unroll
            for (int mt = 0; mt < 4; mt++)
#pragma unroll
                for (int nt = 0; nt < 4; nt++)
                    mma_f16(acc[mt][nt], afr[mt], bfr[nt]);
        }

        // epilogue for this half: streaming float4 stores
        float4 bbv[2];
#pragma unroll
        for (int np = 0; np < 2; np++)
            bbv[np] = *(const float4*)&g_bb[b * NN + j0 + j_w + (2 * nh + np) * 16 + 4 * tig];

#pragma unroll
        for (int mt = 0; mt < 4; mt++) {
#pragma unroll
            for (int rh = 0; rh < 2; rh++) {
                int row = i0 + i_w + mt * 16 + rh * 8 + gid;
                float aa = aav[mt][rh];
                float* Drow = &Dbase[(size_t)row * NN + j0 + j_w + 4 * tig];
#pragma unroll
                for (int np = 0; np < 2; np++) {
                    float4 o;
                    o.x = aa + bbv[np].x - 2.0f * acc[mt][2 * np][rh * 2 + 0];
                    o.y = aa + bbv[np].y - 2.0f * acc[mt][2 * np][rh * 2 + 1];
                    o.z = aa + bbv[np].z - 2.0f * acc[mt][2 * np + 1][rh * 2 + 0];
                    o.w = aa + bbv[np].w - 2.0f * acc[mt][2 * np + 1][rh * 2 + 1];
                    __stcs((float4*)&Drow[(2 * nh + np) * 16], o);
                }
            }
        }
    }
}

// ---------------- launch ----------------

extern "C" void kernel_launch(void* const* d_in, const int* in_sizes, int n_in,
                              void* d_out, int out_size)
{
    const float* a = (const float*)d_in[0];
    const float* b = (const float*)d_in[1];
    float* out = (float*)d_out;

    cudaFuncSetAttribute(distmap_mma_kernel,
                         cudaFuncAttributeMaxDynamicSharedMemorySize, SMEM_TOTAL);

    prep_kernel<<<256, 128>>>(a, b);
    dim3 grid(NN / TILE, NN / TILE, 4);   // (32, 32, 4)
    distmap_mma_kernel<<<grid, NTHREADS, SMEM_TOTAL>>>(out);
}

// round 16
// speedup vs baseline: 1.6390x; 1.1789x over previous
#include <cuda_runtime.h>
#include <cuda_fp16.h>
#include <cstdint>

// DistMap: d[b,i,j] = aa[b,i] + bb[b,j] - 2 * sum_c a[b,c,i]*b[b,c,j]
// a: [B=4, C=64, N=4096] fp32, b: [4, 64, 4096], out: [4, 4096, 4096] fp32
// mma.sync.m16n8k16 fp16 (fp32 accum; fp16 mantissa == tf32 mantissa, N(0,1)).
// Fused prep kernel: per-column exact fp32 norm + packed half2 k-pairs
// (pb carries the logical-n permutation). Main kernel: CTA 128x128, 4 warps
// (64x64 warp tiles), K=64 smem-resident, cp.async.cg tile loads.
// Warp tile processed as FOUR 32x32 chunks (2 m-halves x 2 n-halves):
// live acc = 32 regs -> fits 128-reg cap -> 4 CTAs/SM (16 warps/SM).
// LDT=136 conflict-free fragment LDS. float4 st.global.cs stores.

#define C_DIM 64
#define NN    4096
#define TILE  128
#define NTHREADS 128
#define LDT   136
#define KW    32          // 64 k-values as 32 half2 words

#define SMEM_WORDS (KW * LDT)
#define SMEM_TOTAL (2 * SMEM_WORDS * 4)

// ---------------- device scratch ----------------

__device__ float    g_aa[4 * NN];
__device__ float    g_bb[4 * NN];
__device__ uint32_t g_pa[4 * KW * NN];   // 2 MB
__device__ uint32_t g_pb[4 * KW * NN];   // 2 MB

// ---------------- helpers ----------------

__device__ __forceinline__ uint32_t pack_h2(float x, float y) {
    __half2 h = __floats2half2_rn(x, y);
    return *(uint32_t*)&h;
}

// logical-n permutation (period 64 in j):
__device__ __forceinline__ int perm_n(int j) {
    return (j & ~63) | (16 * ((j >> 4) & 3) + 8 * ((j >> 1) & 1)
                       + 2 * ((j >> 2) & 3) + (j & 1));
}

__device__ __forceinline__ uint32_t smem_u32(const void* p) {
    uint32_t a;
    asm("{ .reg .u64 t; cvta.to.shared.u64 t, %1; cvt.u32.u64 %0, t; }" : "=r"(a) : "l"(p));
    return a;
}

#define CP_ASYNC16(dst, src) \
    asm volatile("cp.async.cg.shared.global [%0], [%1], 16;" :: "r"(dst), "l"(src))
#define CP_COMMIT() asm volatile("cp.async.commit_group;" ::: "memory")
#define CP_WAIT0()  asm volatile("cp.async.wait_group 0;" ::: "memory")

__device__ __forceinline__ void mma_f16(float c[4], const uint32_t a[4], const uint32_t b[2]) {
    asm volatile(
        "mma.sync.aligned.m16n8k16.row.col.f32.f16.f16.f32 "
        "{%0,%1,%2,%3}, {%4,%5,%6,%7}, {%8,%9}, {%0,%1,%2,%3};"
        : "+f"(c[0]), "+f"(c[1]), "+f"(c[2]), "+f"(c[3])
        : "r"(a[0]), "r"(a[1]), "r"(a[2]), "r"(a[3]), "r"(b[0]), "r"(b[1]));
}

// ---------------- fused prep: norms + fp16 pack (+ permutation for b) ----------------

__global__ void prep_kernel(const float* __restrict__ A, const float* __restrict__ B) {
    int idx = blockIdx.x * blockDim.x + threadIdx.x;    // 0..32767
    int which = idx >> 14;                              // 0 = a, 1 = b
    int r   = idx & 16383;                              // b*4096 + col
    int bb  = r >> 12;
    int col = r & 4095;
    const float* src = (which ? B : A) + (size_t)bb * C_DIM * NN + col;

    float v[C_DIM];
    float s = 0.0f;
#pragma unroll
    for (int c = 0; c < C_DIM; c++) {
        v[c] = src[(size_t)c * NN];
        s += v[c] * v[c];
    }

    uint32_t* dst = (which ? g_pb : g_pa) + (size_t)bb * KW * NN;
    int outcol = which ? perm_n(col) : col;
#pragma unroll
    for (int kw = 0; kw < KW; kw++)
        dst[(size_t)kw * NN + outcol] = pack_h2(v[2 * kw], v[2 * kw + 1]);

    (which ? g_bb : g_aa)[r] = s;
}

// ---------------- main kernel ----------------

__global__ __launch_bounds__(NTHREADS, 4)
void distmap_mma_kernel(float* __restrict__ D)   // [4, 4096, 4096]
{
    extern __shared__ __align__(16) char smem[];
    uint32_t* As = (uint32_t*)smem;
    uint32_t* Bs = As + SMEM_WORDS;

    const int tid  = threadIdx.x;
    const int lane = tid & 31;
    const int wid  = tid >> 5;    // 0..3
    const int gid  = lane >> 2;   // 0..7
    const int tig  = lane & 3;    // 0..3
    const int i_w  = (wid >> 1) * 64;
    const int j_w  = (wid & 1) * 64;

    const int b  = blockIdx.z;
    const int i0 = blockIdx.y * TILE;
    const int j0 = blockIdx.x * TILE;

    const uint32_t* pa_b = g_pa + (size_t)b * KW * NN;
    const uint32_t* pb_b = g_pb + (size_t)b * KW * NN;
    const uint32_t as_u = smem_u32(As);
    const uint32_t bs_u = smem_u32(Bs);

    // ---- tile loads: 1024 16B-chunks per tile, 128 threads -> 8 iters ----
#pragma unroll
    for (int it = 0; it < 8; it++) {
        int t  = tid + it * NTHREADS;     // 0..1023
        int kw = t >> 5;
        int ch = (t & 31) << 2;           // word offset (4 words = 16B)
        CP_ASYNC16(as_u + (uint32_t)(kw * LDT + ch) * 4u, pa_b + kw * NN + i0 + ch);
        CP_ASYNC16(bs_u + (uint32_t)(kw * LDT + ch) * 4u, pb_b + kw * NN + j0 + ch);
    }
    CP_COMMIT();
    CP_WAIT0();
    __syncthreads();

    float* Dbase = D + (size_t)b * NN * NN;

    // ---- four 32x32 chunks: 2 m-halves x 2 n-halves ----
#pragma unroll
    for (int mh = 0; mh < 2; mh++) {
#pragma unroll
        for (int nh = 0; nh < 2; nh++) {
            float acc[2][4][4];
#pragma unroll
            for (int mt = 0; mt < 2; mt++)
#pragma unroll
                for (int nt = 0; nt < 4; nt++)
#pragma unroll
                    for (int e = 0; e < 4; e++) acc[mt][nt][e] = 0.0f;

#pragma unroll
            for (int s = 0; s < 4; s++) {
                const int kwb = s * 8;
                uint32_t afr[2][4];
#pragma unroll
                for (int mt = 0; mt < 2; mt++) {
                    int ib = i_w + mh * 32 + mt * 16 + gid;
                    afr[mt][0] = As[(kwb + tig)     * LDT + ib];
                    afr[mt][1] = As[(kwb + tig)     * LDT + ib + 8];
                    afr[mt][2] = As[(kwb + 4 + tig) * LDT + ib];
                    afr[mt][3] = As[(kwb + 4 + tig) * LDT + ib + 8];
                }
                uint32_t bfr[4][2];
#pragma unroll
                for (int nt = 0; nt < 4; nt++) {
                    int jb = j_w + (nh * 4 + nt) * 8 + gid;   // logical n index
                    bfr[nt][0] = Bs[(kwb + tig)     * LDT + jb];
                    bfr[nt][1] = Bs[(kwb + 4 + tig) * LDT + jb];
                }
#pragma unroll
                for (int mt = 0; mt < 2; mt++)
#pragma unroll
                    for (int nt = 0; nt < 4; nt++)
                        mma_f16(acc[mt][nt], afr[mt], bfr[nt]);
            }

            // epilogue for this chunk: streaming float4 stores
            float4 bbv[2];
#pragma unroll
            for (int np = 0; np < 2; np++)
                bbv[np] = *(const float4*)&g_bb[b * NN + j0 + j_w + (2 * nh + np) * 16 + 4 * tig];

#pragma unroll
            for (int mt = 0; mt < 2; mt++) {
                int rbase = i_w + mh * 32 + mt * 16;
                float aa0 = g_aa[b * NN + i0 + rbase + gid];
                float aa1 = g_aa[b * NN + i0 + rbase + 8 + gid];
#pragma unroll
                for (int rh = 0; rh < 2; rh++) {
                    int row = i0 + rbase + rh * 8 + gid;
                    float aa = rh ? aa1 : aa0;
                    float* Drow = &Dbase[(size_t)row * NN + j0 + j_w + 4 * tig];
#pragma unroll
                    for (int np = 0; np < 2; np++) {
                        float4 o;
                        o.x = aa + bbv[np].x - 2.0f * acc[mt][2 * np][rh * 2 + 0];
                        o.y = aa + bbv[np].y - 2.0f * acc[mt][2 * np][rh * 2 + 1];
                        o.z = aa + bbv[np].z - 2.0f * acc[mt][2 * np + 1][rh * 2 + 0];
                        o.w = aa + bbv[np].w - 2.0f * acc[mt][2 * np + 1][rh * 2 + 1];
                        __stcs((float4*)&Drow[(2 * nh + np) * 16], o);
                    }
                }
            }
        }
    }
}

// ---------------- launch ----------------

extern "C" void kernel_launch(void* const* d_in, const int* in_sizes, int n_in,
                              void* d_out, int out_size)
{
    const float* a = (const float*)d_in[0];
    const float* b = (const float*)d_in[1];
    float* out = (float*)d_out;

    cudaFuncSetAttribute(distmap_mma_kernel,
                         cudaFuncAttributeMaxDynamicSharedMemorySize, SMEM_TOTAL);

    prep_kernel<<<256, 128>>>(a, b);
    dim3 grid(NN / TILE, NN / TILE, 4);   // (32, 32, 4)
    distmap_mma_kernel<<<grid, NTHREADS, SMEM_TOTAL>>>(out);
}